// round 2
// baseline (speedup 1.0000x reference)
#include <cuda_runtime.h>

#define NPTS  8192
#define KNN   32
#define NEDGE (NPTS*KNN)        // 262144
#define NOUT  64
#define CAP   4096

// float32 concat layout of the 4-tuple output
#define OFF_ROW ((NEDGE+1)*NOUT)                  // 16777280
#define OFF_COL (OFF_ROW + (NEDGE+1)*KNN)         // 25165920
#define OFF_IJ  (OFF_COL + (NEDGE+1)*KNN)         // 33554560

__device__ float g_x2[NPTS];
__device__ int   g_knn_idx[NEDGE];
__device__ float g_knn_d2[NEDGE];
__device__ int   g_counts[NPTS];
__device__ int   g_offsets[NPTS];
__device__ int   g_cursor[NPTS];
__device__ int   g_bucket[NEDGE];
__device__ int   g_colmat[NEDGE];

// ---------------------------------------------------------------- prep
// x2 = ((rn(x0^2) + rn(x1^2)) + rn(x2^2))  -- XLA mul + sequential reduce, no FMA
__global__ void prep_kernel(const float* __restrict__ coord){
    int j = blockIdx.x*blockDim.x + threadIdx.x;
    if (j < NPTS){
        float a = coord[3*j+0], b = coord[3*j+1], c = coord[3*j+2];
        float s0 = __fmul_rn(a,a);
        float s1 = __fmul_rn(b,b);
        float s2 = __fmul_rn(c,c);
        g_x2[j] = __fadd_rn(__fadd_rn(s0,s1), s2);
        g_counts[j] = 0;
    }
}

// Exact replication of reference d2:
//   dot = fma(x2,y2, fma(x1,y1, rn(x0*y0)))   (ascending-k GEMM accumulation)
//   d2  = rn(rn(x2i+x2j) - rn(2*dot)), clamped at 0
__device__ __forceinline__ float ref_d2(float xi0, float xi1, float xi2, float x2i,
                                        float c0, float c1, float c2, float x2j){
    float dot = __fmul_rn(xi0, c0);
    dot = __fmaf_rn(xi1, c1, dot);
    dot = __fmaf_rn(xi2, c2, dot);
    float t = __fadd_rn(x2i, x2j);
    float u = __fmul_rn(2.0f, dot);          // exact
    float v = __fadd_rn(t, -u);              // rn subtract
    return fmaxf(v, 0.0f);
}

// ---------------------------------------------------------------- KNN
// One block per point. Threshold-filtered exact top-32 by (d2, j) lexicographic.
__global__ void __launch_bounds__(256) knn_kernel(const float* __restrict__ coord,
                                                  float* __restrict__ out){
    const int i    = blockIdx.x;
    const int tid  = threadIdx.x;
    const int lane = tid & 31;
    const int wid  = tid >> 5;

    __shared__ float s_min[256];
    __shared__ float s_T;
    __shared__ int   s_cnt;
    __shared__ float s_cd2[CAP];
    __shared__ int   s_cj[CAP];

    const float xi0 = coord[3*i+0], xi1 = coord[3*i+1], xi2 = coord[3*i+2];
    const float x2i = g_x2[i];

    float d[32];
    float tmin = 3.4e38f;
#pragma unroll
    for (int s = 0; s < 32; s++){
        int j = s*256 + tid;
        float c0 = coord[3*j+0], c1 = coord[3*j+1], c2 = coord[3*j+2];
        float v = ref_d2(xi0, xi1, xi2, x2i, c0, c1, c2, g_x2[j]);
        d[s] = v;
        tmin = fminf(tmin, v);
    }
    s_min[tid] = tmin;
    if (tid == 0) s_cnt = 0;
    __syncthreads();

    // ---- Phase B: warp 0 finds the 32nd-smallest of the 256 thread minima.
    // This is a valid upper bound on the row's 32nd-NN squared distance.
    if (wid == 0){
        float pv = -1.0f; int ps = -1;
        float mv = 3.5e38f; int ms = 0x7fffffff;
#pragma unroll
        for (int s = 0; s < 8; s++){
            int slot = s*32 + lane;
            float v = s_min[slot];
            if (v < mv){ mv = v; ms = slot; }
            else if (v == mv && slot < ms){ ms = slot; }
        }
        float T = 0.0f;
        for (int r = 0; r < 32; r++){
            float rv = mv; int rs = ms;
            for (int o = 16; o; o >>= 1){
                float ov = __shfl_xor_sync(0xffffffffu, rv, o);
                int   os = __shfl_xor_sync(0xffffffffu, rs, o);
                if (ov < rv || (ov == rv && os < rs)){ rv = ov; rs = os; }
            }
            T = rv;
            if (ms == rs){   // this lane owned the extracted min -> rescan
                pv = rv; ps = rs;
                mv = 3.5e38f; ms = 0x7fffffff;
#pragma unroll
                for (int s = 0; s < 8; s++){
                    int slot = s*32 + lane;
                    float v = s_min[slot];
                    bool q = (v > pv) || (v == pv && slot > ps);
                    if (q){
                        if (v < mv){ mv = v; ms = slot; }
                        else if (v == mv && slot < ms){ ms = slot; }
                    }
                }
            }
        }
        if (lane == 0) s_T = T;
    }
    __syncthreads();
    const float T = s_T;

    // ---- Phase C: compact survivors (d2 <= T). Guaranteed >= 32 of them.
#pragma unroll
    for (int s = 0; s < 32; s++){
        if (d[s] <= T){
            int p = atomicAdd(&s_cnt, 1);
            if (p < CAP){ s_cd2[p] = d[s]; s_cj[p] = s*256 + tid; }
        }
    }
    __syncthreads();

    // ---- Phase D: warp 0 exact extraction of 32 smallest (d2, j).
    if (wid == 0){
        int cnt = min(s_cnt, CAP);
        float pv = -1.0f; int pj = -1;
        float mv = 3.5e38f; int mj = 0x7fffffff;
        for (int s = lane; s < cnt; s += 32){
            float v = s_cd2[s]; int j = s_cj[s];
            if (v < mv || (v == mv && j < mj)){ mv = v; mj = j; }
        }
        for (int r = 0; r < 32; r++){
            float rv = mv; int rj = mj;
            for (int o = 16; o; o >>= 1){
                float ov = __shfl_xor_sync(0xffffffffu, rv, o);
                int   oj = __shfl_xor_sync(0xffffffffu, rj, o);
                if (ov < rv || (ov == rv && oj < rj)){ rv = ov; rj = oj; }
            }
            if (mj == rj){   // unique winner lane
                int e = i*KNN + r;
                g_knn_d2[e]  = rv;
                g_knn_idx[e] = rj;
                atomicAdd(&g_counts[rj], 1);
                out[OFF_IJ + 2*e + 0] = (float)i;
                out[OFF_IJ + 2*e + 1] = (float)rj;
                pv = rv; pj = rj;
                mv = 3.5e38f; mj = 0x7fffffff;
                for (int s = lane; s < cnt; s += 32){
                    float v = s_cd2[s]; int j = s_cj[s];
                    bool q = (v > pv) || (v == pv && j > pj);
                    if (q && (v < mv || (v == mv && j < mj))){ mv = v; mj = j; }
                }
            }
        }
    }
}

// ---------------------------------------------------------------- CSR scan
__global__ void scan_kernel(){
    __shared__ int s_sum[256];
    int tid = threadIdx.x;
    int base = tid*32;
    int pre[32];
    int acc = 0;
#pragma unroll
    for (int k = 0; k < 32; k++){
        pre[k] = acc;
        acc += g_counts[base+k];
    }
    s_sum[tid] = acc;
    __syncthreads();
    if (tid == 0){
        int a = 0;
        for (int t = 0; t < 256; t++){ int v = s_sum[t]; s_sum[t] = a; a += v; }
    }
    __syncthreads();
    int tb = s_sum[tid];
#pragma unroll
    for (int k = 0; k < 32; k++){
        int off = tb + pre[k];
        g_offsets[base+k] = off;
        g_cursor[base+k]  = off;
    }
}

// ---------------------------------------------------------------- scatter
__global__ void scatter_kernel(){
    int e = blockIdx.x*blockDim.x + threadIdx.x;
    if (e < NEDGE){
        int t = g_knn_idx[e];
        int p = atomicAdd(&g_cursor[t], 1);
        g_bucket[p] = e;
    }
}

// ---------------------------------------------------------------- colmat
// One warp per target node. Extract incoming edges in ascending key order:
//   count <= 32: key = e            (stable edge-id order, zero-pad tail)
//   count  > 32: key = (d2bits, e)  (lexsort by distance, tie by edge id)
__global__ void __launch_bounds__(256) colmat_kernel(){
    int gw   = (blockIdx.x*blockDim.x + threadIdx.x) >> 5;
    int lane = threadIdx.x & 31;
    if (gw >= NPTS) return;
    int t     = gw;
    int cnt   = g_counts[t];
    int start = g_offsets[t];
    bool heavy = cnt > KNN;

    unsigned long long pk = 0ULL;       // keys are real+1 >= 1
    unsigned long long mk = ~0ULL;
    for (int s = lane; s < cnt; s += 32){
        int e = g_bucket[start+s];
        unsigned long long key;
        if (heavy) key = (((unsigned long long)__float_as_uint(g_knn_d2[e])) << 32) | (unsigned)e;
        else       key = (unsigned long long)(unsigned)e;
        key += 1ULL;
        if (key < mk) mk = key;
    }
    for (int r = 0; r < 32; r++){
        unsigned long long rk = mk;
        for (int o = 16; o; o >>= 1){
            unsigned long long ok = __shfl_xor_sync(0xffffffffu, rk, o);
            if (ok < rk) rk = ok;
        }
        int val = 0;
        if (rk != ~0ULL){
            unsigned long long real = rk - 1ULL;
            unsigned e = heavy ? (unsigned)(real & 0xffffffffULL) : (unsigned)real;
            val = (int)e + 1;
        }
        if (lane == 0) g_colmat[t*KNN + r] = val;
        if (mk == rk && rk != ~0ULL){
            pk = rk;
            mk = ~0ULL;
            for (int s = lane; s < cnt; s += 32){
                int e = g_bucket[start+s];
                unsigned long long key;
                if (heavy) key = (((unsigned long long)__float_as_uint(g_knn_d2[e])) << 32) | (unsigned)e;
                else       key = (unsigned long long)(unsigned)e;
                key += 1ULL;
                if (key > pk && key < mk) mk = key;
            }
        }
    }
}

// ---------------------------------------------------------------- k matrix
__global__ void kfill_kernel(float* __restrict__ out){
    unsigned idx = blockIdx.x*blockDim.x + threadIdx.x;
    if (idx >= (unsigned)(NEDGE+1)*NOUT) return;
    int r = (int)(idx >> 6);
    int c = (int)(idx & 63);
    float v = 0.0f;
    if (r > 0){
        float d2  = g_knn_d2[r-1];
        float sig = 0.1f + (float)c * (4.9f/63.0f);
        float b   = 1.4426950408889634f / (2.0f*sig*sig);  // log2(e)/(2*sig^2)
        float tt  = -d2*b;
        asm("ex2.approx.ftz.f32 %0, %1;" : "=f"(v) : "f"(tt));
    }
    out[idx] = v;
}

// ---------------------------------------------------------------- row_idx + col_idx
__global__ void idxfill_kernel(float* __restrict__ out){
    int idx = blockIdx.x*blockDim.x + threadIdx.x;
    if (idx >= (NEDGE+1)*KNN) return;
    int r = idx >> 5, c = idx & 31;
    float rv = 0.0f, cv = 0.0f;
    if (r > 0){
        int e = r - 1;
        int k = (e & ~31) + c;        // (e>>5)*32 + c
        rv = (float)k;
        cv = (float)g_colmat[k];
    }
    out[OFF_ROW + idx] = rv;
    out[OFF_COL + idx] = cv;
}

// ---------------------------------------------------------------- launch
extern "C" void kernel_launch(void* const* d_in, const int* in_sizes, int n_in,
                              void* d_out, int out_size){
    const float* coord = (const float*)d_in[0];
    float* out = (float*)d_out;

    prep_kernel   <<<(NPTS+255)/256, 256>>>(coord);
    knn_kernel    <<<NPTS, 256>>>(coord, out);
    scan_kernel   <<<1, 256>>>();
    scatter_kernel<<<NEDGE/256, 256>>>();
    colmat_kernel <<<NPTS/8, 256>>>();
    kfill_kernel  <<<((NEDGE+1)*NOUT + 255)/256, 256>>>(out);
    idxfill_kernel<<<((NEDGE+1)*KNN  + 255)/256, 256>>>(out);
}

// round 3
// speedup vs baseline: 2.5173x; 2.5173x over previous
#include <cuda_runtime.h>

#define NPTS  8192
#define KNN   32
#define NEDGE (NPTS*KNN)        // 262144
#define NOUT  64
#define CAP   2048

// float32 concat layout of the 4-tuple output
#define OFF_ROW ((NEDGE+1)*NOUT)                  // 16777280
#define OFF_COL (OFF_ROW + (NEDGE+1)*KNN)         // 25165920
#define OFF_IJ  (OFF_COL + (NEDGE+1)*KNN)         // 33554560

__device__ float4 g_pts[NPTS];               // {x, y, z, x2}
__device__ float  g_bcoef[NOUT];             // log2(e) / (2*sigma_c^2)
__device__ int    g_knn_idx[NEDGE];
__device__ float  g_knn_d2[NEDGE];
__device__ int    g_counts[NPTS];
__device__ int    g_offsets[NPTS];
__device__ int    g_cursor[NPTS];
__device__ int    g_bucket[NEDGE];
__device__ __align__(16) int g_colmat[NEDGE];

// ---------------------------------------------------------------- prep
// x2 = ((rn(x0^2) + rn(x1^2)) + rn(x2^2))  -- XLA mul + sequential reduce
__global__ void prep_kernel(const float* __restrict__ coord){
    int j = blockIdx.x*blockDim.x + threadIdx.x;
    if (j < NPTS){
        float a = coord[3*j+0], b = coord[3*j+1], c = coord[3*j+2];
        float s0 = __fmul_rn(a,a);
        float s1 = __fmul_rn(b,b);
        float s2 = __fmul_rn(c,c);
        float x2 = __fadd_rn(__fadd_rn(s0,s1), s2);
        g_pts[j] = make_float4(a, b, c, x2);
        g_counts[j] = 0;
    }
    if (j < NOUT){
        float sig = 0.1f + (float)j * (4.9f/63.0f);
        g_bcoef[j] = 1.4426950408889634f / (2.0f*sig*sig);
    }
}

// ---------------------------------------------------------------- KNN
// One block per query point.
//  A: each thread computes 32 distances (float4 loads, exact ref arithmetic)
//  B: threshold T = max over 32 groups(8 threads) of group-min  (>=32 below T)
//  C: compact survivors as 64-bit keys (d2bits<<32)|j into smem
//  D: rank-by-counting -> direct scatter of the 32 smallest (d2, j)
__global__ void __launch_bounds__(256) knn_kernel(float* __restrict__ out){
    const int i    = blockIdx.x;
    const int tid  = threadIdx.x;
    const int lane = tid & 31;
    const int wid  = tid >> 5;

    __shared__ float s_min[256];
    __shared__ float s_T;
    __shared__ int   s_cnt;
    __shared__ unsigned long long s_key[CAP];

    const float4 q = g_pts[i];
    const float4* __restrict__ p = g_pts + tid;

    float d[32];
    float tmin = 3.4e38f;
#pragma unroll
    for (int s = 0; s < 32; s++){
        float4 c = p[s*256];
        float dot = __fmul_rn(q.x, c.x);
        dot = __fmaf_rn(q.y, c.y, dot);
        dot = __fmaf_rn(q.z, c.z, dot);
        float t = __fadd_rn(q.w, c.w);
        float v = __fmaf_rn(-2.0f, dot, t);   // == rn(t - rn(2*dot)), 2*dot exact
        v = fmaxf(v, 0.0f);
        d[s] = v;
        tmin = fminf(tmin, v);
    }
    s_min[tid] = tmin;
    if (tid == 0) s_cnt = 0;
    __syncthreads();

    // Phase B: T = max over 32 groups of (min over the group's 8 thread-minima).
    // Each group covers 256 distinct candidates -> at least 32 survivors <= T.
    if (wid == 0){
        float gmin = 3.4e38f;
#pragma unroll
        for (int k = 0; k < 8; k++) gmin = fminf(gmin, s_min[lane*8 + k]);
#pragma unroll
        for (int o = 16; o; o >>= 1)
            gmin = fmaxf(gmin, __shfl_xor_sync(0xffffffffu, gmin, o));
        if (lane == 0) s_T = gmin;
    }
    __syncthreads();
    const float T = s_T;

    // Phase C: compact survivors.
#pragma unroll
    for (int s = 0; s < 32; s++){
        if (d[s] <= T){
            int pos = atomicAdd(&s_cnt, 1);
            if (pos < CAP)
                s_key[pos] = (((unsigned long long)__float_as_uint(d[s])) << 32)
                           | (unsigned)(s*256 + tid);
        }
    }
    __syncthreads();

    // Phase D: rank by counting (keys unique: j distinct). Order-invariant.
    int cnt = min(s_cnt, CAP);
    for (int s0 = tid; s0 < cnt; s0 += 256){
        unsigned long long my = s_key[s0];
        int rank = 0;
        for (int k = 0; k < cnt; k++) rank += (s_key[k] < my);
        if (rank < KNN){
            int   j  = (int)(unsigned)(my & 0xffffffffULL);
            float d2 = __uint_as_float((unsigned)(my >> 32));
            int e = i*KNN + rank;
            g_knn_d2[e]  = d2;
            g_knn_idx[e] = j;
            atomicAdd(&g_counts[j], 1);
            out[OFF_IJ + 2*e + 0] = (float)i;
            out[OFF_IJ + 2*e + 1] = (float)j;
        }
    }
}

// ---------------------------------------------------------------- CSR scan
__global__ void scan_kernel(){
    __shared__ int s_sum[256];
    int tid = threadIdx.x;
    int base = tid*32;
    int pre[32];
    int acc = 0;
#pragma unroll
    for (int k = 0; k < 32; k++){
        pre[k] = acc;
        acc += g_counts[base+k];
    }
    s_sum[tid] = acc;
    __syncthreads();
    if (tid == 0){
        int a = 0;
        for (int t = 0; t < 256; t++){ int v = s_sum[t]; s_sum[t] = a; a += v; }
    }
    __syncthreads();
    int tb = s_sum[tid];
#pragma unroll
    for (int k = 0; k < 32; k++){
        int off = tb + pre[k];
        g_offsets[base+k] = off;
        g_cursor[base+k]  = off;
    }
}

// ---------------------------------------------------------------- scatter
__global__ void scatter_kernel(){
    int e = blockIdx.x*blockDim.x + threadIdx.x;
    if (e < NEDGE){
        int t = g_knn_idx[e];
        int p = atomicAdd(&g_cursor[t], 1);
        g_bucket[p] = e;
    }
}

// ---------------------------------------------------------------- colmat
// One warp per target node. Extract incoming edges in ascending key order:
//   count <= 32: key = e            (stable edge-id order, zero-pad tail)
//   count  > 32: key = (d2bits, e)  (lexsort by distance, tie by edge id)
__global__ void __launch_bounds__(256) colmat_kernel(){
    int gw   = (blockIdx.x*blockDim.x + threadIdx.x) >> 5;
    int lane = threadIdx.x & 31;
    if (gw >= NPTS) return;
    int t     = gw;
    int cnt   = g_counts[t];
    int start = g_offsets[t];
    bool heavy = cnt > KNN;

    unsigned long long pk = 0ULL;       // keys are real+1 >= 1
    unsigned long long mk = ~0ULL;
    for (int s = lane; s < cnt; s += 32){
        int e = g_bucket[start+s];
        unsigned long long key;
        if (heavy) key = (((unsigned long long)__float_as_uint(g_knn_d2[e])) << 32) | (unsigned)e;
        else       key = (unsigned long long)(unsigned)e;
        key += 1ULL;
        if (key < mk) mk = key;
    }
    for (int r = 0; r < 32; r++){
        unsigned long long rk = mk;
        for (int o = 16; o; o >>= 1){
            unsigned long long ok = __shfl_xor_sync(0xffffffffu, rk, o);
            if (ok < rk) rk = ok;
        }
        int val = 0;
        if (rk != ~0ULL){
            unsigned long long real = rk - 1ULL;
            unsigned e = heavy ? (unsigned)(real & 0xffffffffULL) : (unsigned)real;
            val = (int)e + 1;
        }
        if (lane == 0) g_colmat[t*KNN + r] = val;
        if (mk == rk && rk != ~0ULL){
            pk = rk;
            mk = ~0ULL;
            for (int s = lane; s < cnt; s += 32){
                int e = g_bucket[start+s];
                unsigned long long key;
                if (heavy) key = (((unsigned long long)__float_as_uint(g_knn_d2[e])) << 32) | (unsigned)e;
                else       key = (unsigned long long)(unsigned)e;
                key += 1ULL;
                if (key > pk && key < mk) mk = key;
            }
        }
    }
}

// ---------------------------------------------------------------- k matrix (float4 stores)
// quads: (NEDGE+1)*16
__global__ void kfill_kernel(float* __restrict__ out){
    int idx = blockIdx.x*blockDim.x + threadIdx.x;
    if (idx >= (NEDGE+1)*16) return;
    int r  = idx >> 4;
    int c4 = (idx & 15) << 2;
    float4 v = make_float4(0.f, 0.f, 0.f, 0.f);
    if (r > 0){
        float d2 = g_knn_d2[r-1];
        const float4 b = *(const float4*)&g_bcoef[c4];
        asm("ex2.approx.ftz.f32 %0, %1;" : "=f"(v.x) : "f"(-d2*b.x));
        asm("ex2.approx.ftz.f32 %0, %1;" : "=f"(v.y) : "f"(-d2*b.y));
        asm("ex2.approx.ftz.f32 %0, %1;" : "=f"(v.z) : "f"(-d2*b.z));
        asm("ex2.approx.ftz.f32 %0, %1;" : "=f"(v.w) : "f"(-d2*b.w));
    }
    *(float4*)&out[idx << 2] = v;
}

// ---------------------------------------------------------------- row_idx + col_idx (float4 stores)
// quads per array: (NEDGE+1)*8
__global__ void idxfill_kernel(float* __restrict__ out){
    int idx = blockIdx.x*blockDim.x + threadIdx.x;
    if (idx >= (NEDGE+1)*8) return;
    int r = idx >> 3;
    int qc = (idx & 7) << 2;
    float4 rv = make_float4(0.f,0.f,0.f,0.f);
    float4 cv = make_float4(0.f,0.f,0.f,0.f);
    if (r > 0){
        int e = r - 1;
        int k = (e & ~31) + qc;
        rv = make_float4((float)k, (float)(k+1), (float)(k+2), (float)(k+3));
        int4 cm = *(const int4*)&g_colmat[k];
        cv = make_float4((float)cm.x, (float)cm.y, (float)cm.z, (float)cm.w);
    }
    *(float4*)&out[OFF_ROW + (idx << 2)] = rv;
    *(float4*)&out[OFF_COL + (idx << 2)] = cv;
}

// ---------------------------------------------------------------- launch
extern "C" void kernel_launch(void* const* d_in, const int* in_sizes, int n_in,
                              void* d_out, int out_size){
    const float* coord = (const float*)d_in[0];
    float* out = (float*)d_out;

    prep_kernel   <<<(NPTS+255)/256, 256>>>(coord);
    knn_kernel    <<<NPTS, 256>>>(out);
    scan_kernel   <<<1, 256>>>();
    scatter_kernel<<<NEDGE/256, 256>>>();
    colmat_kernel <<<NPTS/8, 256>>>();
    kfill_kernel  <<<((NEDGE+1)*16 + 255)/256, 256>>>(out);
    idxfill_kernel<<<((NEDGE+1)*8  + 255)/256, 256>>>(out);
}

// round 4
// speedup vs baseline: 3.7916x; 1.5062x over previous
#include <cuda_runtime.h>

#define NPTS  8192
#define KNN   32
#define NEDGE (NPTS*KNN)        // 262144
#define NOUT  64
#define QB    8                 // queries per knn block
#define CAPQ  512               // survivor capacity per query
#define COLCAP 192              // colmat smem capacity per node

// float32 concat layout of the 4-tuple output
#define OFF_ROW ((NEDGE+1)*NOUT)                  // 16777280
#define OFF_COL (OFF_ROW + (NEDGE+1)*KNN)         // 25165920
#define OFF_IJ  (OFF_COL + (NEDGE+1)*KNN)         // 33554560

__device__ float4 g_pts[NPTS];               // {x, y, z, x2}
__device__ float  g_bcoef[NOUT];             // log2(e) / (2*sigma_c^2)
__device__ int    g_knn_idx[NEDGE];
__device__ float  g_knn_d2[NEDGE];
__device__ int    g_cincol[NEDGE];           // arrival rank within target column
__device__ int    g_counts[NPTS];
__device__ int    g_offsets[NPTS];
__device__ int    g_bucket[NEDGE];
__device__ __align__(16) int g_colmat[NEDGE];

// exact reference fp32 distance:
// dot = fma(z, fma(y, rn(x*x))) ; d2 = rn(rn(x2i+x2j) - rn(2*dot)) ; clamp 0
__device__ __forceinline__ float ref_d2(const float4 q, const float4 c){
    float dot = __fmul_rn(q.x, c.x);
    dot = __fmaf_rn(q.y, c.y, dot);
    dot = __fmaf_rn(q.z, c.z, dot);
    float t = __fadd_rn(q.w, c.w);
    float v = __fmaf_rn(-2.0f, dot, t);   // == rn(t - rn(2*dot)); 2*dot exact
    return fmaxf(v, 0.0f);
}

// ---------------------------------------------------------------- prep
// x2 = ((rn(x0^2) + rn(x1^2)) + rn(x2^2))  -- XLA mul + sequential reduce
__global__ void prep_kernel(const float* __restrict__ coord){
    int j = blockIdx.x*blockDim.x + threadIdx.x;
    if (j < NPTS){
        float a = coord[3*j+0], b = coord[3*j+1], c = coord[3*j+2];
        float s0 = __fmul_rn(a,a);
        float s1 = __fmul_rn(b,b);
        float s2 = __fmul_rn(c,c);
        float x2 = __fadd_rn(__fadd_rn(s0,s1), s2);
        g_pts[j] = make_float4(a, b, c, x2);
        g_counts[j] = 0;
    }
    if (j < NOUT){
        float sig = 0.1f + (float)j * (4.9f/63.0f);
        g_bcoef[j] = 1.4426950408889634f / (2.0f*sig*sig);
    }
}

// ---------------------------------------------------------------- KNN
// 8 queries per block. Pass 1: per-thread mins. Threshold per query (warp q):
// T = 32nd-smallest of 64 group-mins (4-thread groups; each covers 128
// disjoint candidates => >=32 survivors <= T guaranteed). Pass 2: recompute,
// compact survivors. Phase D: rank-by-counting -> scatter 32 smallest (d2,j).
__global__ void __launch_bounds__(256) knn_kernel(float* __restrict__ out){
    const int i0   = blockIdx.x * QB;
    const int tid  = threadIdx.x;
    const int lane = tid & 31;
    const int wid  = tid >> 5;

    __shared__ float s_min[QB*256];
    __shared__ float s_T[QB];
    __shared__ int   s_cnt[QB];
    __shared__ unsigned long long s_key[QB*CAPQ];

    float4 Q[QB];
#pragma unroll
    for (int q = 0; q < QB; q++) Q[q] = g_pts[i0 + q];

    const float4* __restrict__ p = g_pts + tid;

    if (tid < QB) s_cnt[tid] = 0;

    // ---- Pass 1: per-thread min over this thread's 32 candidates, per query
    float tmin[QB];
#pragma unroll
    for (int q = 0; q < QB; q++) tmin[q] = 3.4e38f;
#pragma unroll 8
    for (int s = 0; s < 32; s++){
        float4 c = p[s*256];
#pragma unroll
        for (int q = 0; q < QB; q++){
            float v = ref_d2(Q[q], c);
            tmin[q] = fminf(tmin[q], v);
        }
    }
#pragma unroll
    for (int q = 0; q < QB; q++) s_min[q*256 + tid] = tmin[q];
    __syncthreads();

    // ---- Threshold: warp w handles query w. 64 groups of 4 threads.
    {
        const int q = wid;
        const float* sm = s_min + q*256;
        float ga = fminf(fminf(sm[lane*4+0], sm[lane*4+1]),
                         fminf(sm[lane*4+2], sm[lane*4+3]));
        float gb = fminf(fminf(sm[128+lane*4+0], sm[128+lane*4+1]),
                         fminf(sm[128+lane*4+2], sm[128+lane*4+3]));
        unsigned long long ka = (((unsigned long long)__float_as_uint(ga)) << 6) | (unsigned)lane;
        unsigned long long kb = (((unsigned long long)__float_as_uint(gb)) << 6) | (unsigned)(lane+32);
        unsigned long long* gk = s_key + q*CAPQ;   // scratch (dead after T)
        gk[lane]      = ka;
        gk[lane + 32] = kb;
        __syncwarp();
        int ra = 0, rb = 0;
#pragma unroll
        for (int k = 0; k < 64; k++){
            unsigned long long o = gk[k];
            ra += (o < ka);
            rb += (o < kb);
        }
        if (ra == 31) s_T[q] = ga;
        if (rb == 31) s_T[q] = gb;
    }
    __syncthreads();

    float Tq[QB];
#pragma unroll
    for (int q = 0; q < QB; q++) Tq[q] = s_T[q];

    // ---- Pass 2: recompute, compact survivors (expected ~45 per query)
#pragma unroll 8
    for (int s = 0; s < 32; s++){
        float4 c = p[s*256];
        unsigned j = (unsigned)(s*256 + tid);
#pragma unroll
        for (int q = 0; q < QB; q++){
            float v = ref_d2(Q[q], c);
            if (v <= Tq[q]){
                int pos = atomicAdd(&s_cnt[q], 1);
                if (pos < CAPQ)
                    s_key[q*CAPQ + pos] =
                        (((unsigned long long)__float_as_uint(v)) << 32) | j;
            }
        }
    }
    __syncthreads();

    // ---- Phase D: rank by counting (keys unique via j). Order-invariant.
#pragma unroll
    for (int q = 0; q < QB; q++){
        int cnt = min(s_cnt[q], CAPQ);
        const unsigned long long* keys = s_key + q*CAPQ;
        for (int s0 = tid; s0 < cnt; s0 += 256){
            unsigned long long my = keys[s0];
            int rank = 0;
            for (int k = 0; k < cnt; k++) rank += (keys[k] < my);
            if (rank < KNN){
                int   j  = (int)(unsigned)(my & 0xffffffffULL);
                float d2 = __uint_as_float((unsigned)(my >> 32));
                int e = (i0 + q)*KNN + rank;
                g_knn_d2[e]  = d2;
                g_knn_idx[e] = j;
                int pos = atomicAdd(&g_counts[j], 1);
                g_cincol[e] = pos;
                out[OFF_IJ + 2*e + 0] = (float)(i0 + q);
                out[OFF_IJ + 2*e + 1] = (float)j;
            }
        }
    }
}

// ---------------------------------------------------------------- CSR scan
__global__ void scan_kernel(){
    __shared__ int s_sum[256];
    int tid = threadIdx.x;
    int base = tid*32;
    int pre[32];
    int acc = 0;
#pragma unroll
    for (int k = 0; k < 32; k++){
        pre[k] = acc;
        acc += g_counts[base+k];
    }
    s_sum[tid] = acc;
    __syncthreads();
    if (tid == 0){
        int a = 0;
        for (int t = 0; t < 256; t++){ int v = s_sum[t]; s_sum[t] = a; a += v; }
    }
    __syncthreads();
    int tb = s_sum[tid];
#pragma unroll
    for (int k = 0; k < 32; k++){
        g_offsets[base+k] = tb + pre[k];
    }
}

// ---------------------------------------------------------------- scatter (no atomics)
__global__ void scatter_kernel(){
    int e = blockIdx.x*blockDim.x + threadIdx.x;
    if (e < NEDGE){
        int t = g_knn_idx[e];
        g_bucket[g_offsets[t] + g_cincol[e]] = e;
    }
}

// ---------------------------------------------------------------- colmat
// One warp per target node. Rank-by-counting over incoming-edge keys:
//   count <= 32: key = e            (stable edge-id order, zero-pad tail)
//   count  > 32: key = (d2bits, e)  (lexsort by distance, tie by edge id)
__global__ void __launch_bounds__(256) colmat_kernel(){
    __shared__ unsigned long long s_ck[8][COLCAP];
    int gw   = (blockIdx.x*blockDim.x + threadIdx.x) >> 5;
    int lane = threadIdx.x & 31;
    int wloc = (threadIdx.x >> 5);
    if (gw >= NPTS) return;
    int t     = gw;
    int cnt   = g_counts[t];
    int start = g_offsets[t];
    bool heavy = cnt > KNN;

    if (cnt <= COLCAP){
        for (int s = lane; s < cnt; s += 32){
            int e = g_bucket[start+s];
            unsigned long long key;
            if (heavy) key = (((unsigned long long)__float_as_uint(g_knn_d2[e])) << 32) | (unsigned)e;
            else       key = (unsigned long long)(unsigned)e;
            s_ck[wloc][s] = key;
        }
        g_colmat[t*KNN + lane] = 0;
        __syncwarp();
        for (int s = lane; s < cnt; s += 32){
            unsigned long long my = s_ck[wloc][s];
            int rank = 0;
            for (int k = 0; k < cnt; k++) rank += (s_ck[wloc][k] < my);
            if (rank < KNN){
                unsigned e = heavy ? (unsigned)(my & 0xffffffffULL) : (unsigned)my;
                g_colmat[t*KNN + rank] = (int)e + 1;
            }
        }
    } else {
        // rare fallback: serial extract-min (order-invariant)
        unsigned long long pk = 0ULL;
        unsigned long long mk = ~0ULL;
        for (int s = lane; s < cnt; s += 32){
            int e = g_bucket[start+s];
            unsigned long long key = (((unsigned long long)__float_as_uint(g_knn_d2[e])) << 32) | (unsigned)e;
            key += 1ULL;
            if (key < mk) mk = key;
        }
        for (int r = 0; r < 32; r++){
            unsigned long long rk = mk;
            for (int o = 16; o; o >>= 1){
                unsigned long long ok = __shfl_xor_sync(0xffffffffu, rk, o);
                if (ok < rk) rk = ok;
            }
            int val = 0;
            if (rk != ~0ULL)
                val = (int)(unsigned)((rk - 1ULL) & 0xffffffffULL) + 1;
            if (lane == 0) g_colmat[t*KNN + r] = val;
            if (mk == rk && rk != ~0ULL){
                pk = rk;
                mk = ~0ULL;
                for (int s = lane; s < cnt; s += 32){
                    int e = g_bucket[start+s];
                    unsigned long long key = (((unsigned long long)__float_as_uint(g_knn_d2[e])) << 32) | (unsigned)e;
                    key += 1ULL;
                    if (key > pk && key < mk) mk = key;
                }
            }
        }
    }
}

// ---------------------------------------------------------------- k matrix (float4 stores)
__global__ void kfill_kernel(float* __restrict__ out){
    int idx = blockIdx.x*blockDim.x + threadIdx.x;
    if (idx >= (NEDGE+1)*16) return;
    int r  = idx >> 4;
    int c4 = (idx & 15) << 2;
    float4 v = make_float4(0.f, 0.f, 0.f, 0.f);
    if (r > 0){
        float d2 = g_knn_d2[r-1];
        const float4 b = *(const float4*)&g_bcoef[c4];
        asm("ex2.approx.ftz.f32 %0, %1;" : "=f"(v.x) : "f"(-d2*b.x));
        asm("ex2.approx.ftz.f32 %0, %1;" : "=f"(v.y) : "f"(-d2*b.y));
        asm("ex2.approx.ftz.f32 %0, %1;" : "=f"(v.z) : "f"(-d2*b.z));
        asm("ex2.approx.ftz.f32 %0, %1;" : "=f"(v.w) : "f"(-d2*b.w));
    }
    *(float4*)&out[idx << 2] = v;
}

// ---------------------------------------------------------------- row_idx + col_idx (float4 stores)
__global__ void idxfill_kernel(float* __restrict__ out){
    int idx = blockIdx.x*blockDim.x + threadIdx.x;
    if (idx >= (NEDGE+1)*8) return;
    int r = idx >> 3;
    int qc = (idx & 7) << 2;
    float4 rv = make_float4(0.f,0.f,0.f,0.f);
    float4 cv = make_float4(0.f,0.f,0.f,0.f);
    if (r > 0){
        int e = r - 1;
        int k = (e & ~31) + qc;
        rv = make_float4((float)k, (float)(k+1), (float)(k+2), (float)(k+3));
        int4 cm = *(const int4*)&g_colmat[k];
        cv = make_float4((float)cm.x, (float)cm.y, (float)cm.z, (float)cm.w);
    }
    *(float4*)&out[OFF_ROW + (idx << 2)] = rv;
    *(float4*)&out[OFF_COL + (idx << 2)] = cv;
}

// ---------------------------------------------------------------- launch
extern "C" void kernel_launch(void* const* d_in, const int* in_sizes, int n_in,
                              void* d_out, int out_size){
    const float* coord = (const float*)d_in[0];
    float* out = (float*)d_out;

    prep_kernel   <<<(NPTS+255)/256, 256>>>(coord);
    knn_kernel    <<<NPTS/QB, 256>>>(out);
    scan_kernel   <<<1, 256>>>();
    scatter_kernel<<<NEDGE/256, 256>>>();
    colmat_kernel <<<NPTS/8, 256>>>();
    kfill_kernel  <<<((NEDGE+1)*16 + 255)/256, 256>>>(out);
    idxfill_kernel<<<((NEDGE+1)*8  + 255)/256, 256>>>(out);
}

// round 5
// speedup vs baseline: 4.0533x; 1.0690x over previous
#include <cuda_runtime.h>

#define NPTS  8192
#define KNN   32
#define NEDGE (NPTS*KNN)        // 262144
#define NOUT  64
#define QB    8                 // queries per knn block
#define CAPQ  512               // survivor capacity per query
#define COLCAP 192              // colmat smem capacity per node
#define TMARGIN 0.01f           // proxy-threshold safety margin

// float32 concat layout of the 4-tuple output
#define OFF_ROW ((NEDGE+1)*NOUT)                  // 16777280
#define OFF_COL (OFF_ROW + (NEDGE+1)*KNN)         // 25165920
#define OFF_IJ  (OFF_COL + (NEDGE+1)*KNN)         // 33554560

__device__ float4 g_pts[NPTS];               // {x, y, z, x2}
__device__ float  g_bcoef[NOUT];             // log2(e) / (2*sigma_c^2)
__device__ int    g_knn_idx[NEDGE];
__device__ float  g_knn_d2[NEDGE];
__device__ int    g_cincol[NEDGE];           // arrival rank within target column
__device__ int    g_counts[NPTS];
__device__ int    g_offsets[NPTS];
__device__ int    g_bucket[NEDGE];
__device__ __align__(16) int g_colmat[NEDGE];

// exact reference fp32 distance:
// dot = fma(z, fma(y, rn(x*x))) ; d2 = rn(rn(x2i+x2j) - rn(2*dot)) ; clamp 0
__device__ __forceinline__ float ref_d2(const float4 q, const float4 c){
    float dot = __fmul_rn(q.x, c.x);
    dot = __fmaf_rn(q.y, c.y, dot);
    dot = __fmaf_rn(q.z, c.z, dot);
    float t = __fadd_rn(q.w, c.w);
    float v = __fmaf_rn(-2.0f, dot, t);   // == rn(t - rn(2*dot)); 2*dot exact
    return fmaxf(v, 0.0f);
}

// 3-FMA proxy: u = -2qx*cx -2qy*cy -2qz*cz + x2j  ~= d2 - x2i  (+-5e-4)
__device__ __forceinline__ float proxy_u(const float4 m, const float4 c){
    return __fmaf_rn(m.x, c.x, __fmaf_rn(m.y, c.y, __fmaf_rn(m.z, c.z, c.w)));
}

// monotone float -> uint (handles negatives) for unsigned ranking
__device__ __forceinline__ unsigned f2mono(float f){
    unsigned b = __float_as_uint(f);
    return b ^ (((int)b >> 31) | 0x80000000u);
}

// ---------------------------------------------------------------- prep
// x2 = ((rn(x0^2) + rn(x1^2)) + rn(x2^2))  -- XLA mul + sequential reduce
__global__ void prep_kernel(const float* __restrict__ coord){
    int j = blockIdx.x*blockDim.x + threadIdx.x;
    if (j < NPTS){
        float a = coord[3*j+0], b = coord[3*j+1], c = coord[3*j+2];
        float s0 = __fmul_rn(a,a);
        float s1 = __fmul_rn(b,b);
        float s2 = __fmul_rn(c,c);
        float x2 = __fadd_rn(__fadd_rn(s0,s1), s2);
        g_pts[j] = make_float4(a, b, c, x2);
        g_counts[j] = 0;
    }
    if (j < NOUT){
        float sig = 0.1f + (float)j * (4.9f/63.0f);
        g_bcoef[j] = 1.4426950408889634f / (2.0f*sig*sig);
    }
}

// ---------------------------------------------------------------- KNN
// 8 queries per block, 3-FMA proxy scans.
//  Pass 1: per-thread min of proxy u over 32 candidates, per query.
//  Threshold (warp q): T = 32nd-smallest of 64 group-mins (4-thread groups,
//    each covering 128 disjoint candidates => >=32 survivors u<=T), +margin.
//  Pass 2: recompute proxy; survivors get exact ref_d2; compact as keys.
//  Phase D: rank-by-counting -> scatter the 32 smallest (d2, j).
__global__ void __launch_bounds__(256) knn_kernel(float* __restrict__ out){
    const int i0   = blockIdx.x * QB;
    const int tid  = threadIdx.x;
    const int lane = tid & 31;
    const int wid  = tid >> 5;

    __shared__ float s_min[QB*256];
    __shared__ float s_T[QB];
    __shared__ int   s_cnt[QB];
    __shared__ unsigned long long s_key[QB*CAPQ];

    float4 Q[QB], M[QB];
#pragma unroll
    for (int q = 0; q < QB; q++){
        Q[q] = g_pts[i0 + q];
        M[q] = make_float4(-2.0f*Q[q].x, -2.0f*Q[q].y, -2.0f*Q[q].z, 0.f);
    }

    const float4* __restrict__ p = g_pts + tid;

    if (tid < QB) s_cnt[tid] = 0;

    // ---- Pass 1: per-thread proxy min per query
    float tmin[QB];
#pragma unroll
    for (int q = 0; q < QB; q++) tmin[q] = 3.4e38f;
#pragma unroll 8
    for (int s = 0; s < 32; s++){
        float4 c = p[s*256];
#pragma unroll
        for (int q = 0; q < QB; q++)
            tmin[q] = fminf(tmin[q], proxy_u(M[q], c));
    }
#pragma unroll
    for (int q = 0; q < QB; q++) s_min[q*256 + tid] = tmin[q];
    __syncthreads();

    // ---- Threshold: warp w handles query w. 64 groups of 4 threads.
    {
        const int q = wid;
        const float* sm = s_min + q*256;
        float ga = fminf(fminf(sm[lane*4+0], sm[lane*4+1]),
                         fminf(sm[lane*4+2], sm[lane*4+3]));
        float gb = fminf(fminf(sm[128+lane*4+0], sm[128+lane*4+1]),
                         fminf(sm[128+lane*4+2], sm[128+lane*4+3]));
        unsigned long long ka = (((unsigned long long)f2mono(ga)) << 6) | (unsigned)lane;
        unsigned long long kb = (((unsigned long long)f2mono(gb)) << 6) | (unsigned)(lane+32);
        unsigned long long* gk = s_key + q*CAPQ;   // scratch (dead after T)
        gk[lane]      = ka;
        gk[lane + 32] = kb;
        __syncwarp();
        int ra = 0, rb = 0;
#pragma unroll
        for (int k = 0; k < 64; k++){
            unsigned long long o = gk[k];
            ra += (o < ka);
            rb += (o < kb);
        }
        if (ra == 31) s_T[q] = ga;
        if (rb == 31) s_T[q] = gb;
    }
    __syncthreads();

    float Tq[QB];
#pragma unroll
    for (int q = 0; q < QB; q++) Tq[q] = s_T[q] + TMARGIN;

    // ---- Pass 2: proxy scan; survivors get exact d2 and are compacted
#pragma unroll 8
    for (int s = 0; s < 32; s++){
        float4 c = p[s*256];
        unsigned j = (unsigned)(s*256 + tid);
#pragma unroll
        for (int q = 0; q < QB; q++){
            float u = proxy_u(M[q], c);
            if (u <= Tq[q]){
                float d2 = ref_d2(Q[q], c);     // exact reference value
                int pos = atomicAdd(&s_cnt[q], 1);
                if (pos < CAPQ)
                    s_key[q*CAPQ + pos] =
                        (((unsigned long long)__float_as_uint(d2)) << 32) | j;
            }
        }
    }
    __syncthreads();

    // ---- Phase D: rank by counting (keys unique via j). Order-invariant.
#pragma unroll
    for (int q = 0; q < QB; q++){
        int cnt = min(s_cnt[q], CAPQ);
        const unsigned long long* keys = s_key + q*CAPQ;
        for (int s0 = tid; s0 < cnt; s0 += 256){
            unsigned long long my = keys[s0];
            int rank = 0;
            for (int k = 0; k < cnt; k++) rank += (keys[k] < my);
            if (rank < KNN){
                int   j  = (int)(unsigned)(my & 0xffffffffULL);
                float d2 = __uint_as_float((unsigned)(my >> 32));
                int e = (i0 + q)*KNN + rank;
                g_knn_d2[e]  = d2;
                g_knn_idx[e] = j;
                int pos = atomicAdd(&g_counts[j], 1);
                g_cincol[e] = pos;
                out[OFF_IJ + 2*e + 0] = (float)(i0 + q);
                out[OFF_IJ + 2*e + 1] = (float)j;
            }
        }
    }
}

// ---------------------------------------------------------------- CSR scan
__global__ void scan_kernel(){
    __shared__ int s_sum[256];
    int tid = threadIdx.x;
    int base = tid*32;
    int pre[32];
    int acc = 0;
#pragma unroll
    for (int k = 0; k < 32; k++){
        pre[k] = acc;
        acc += g_counts[base+k];
    }
    s_sum[tid] = acc;
    __syncthreads();
    if (tid == 0){
        int a = 0;
        for (int t = 0; t < 256; t++){ int v = s_sum[t]; s_sum[t] = a; a += v; }
    }
    __syncthreads();
    int tb = s_sum[tid];
#pragma unroll
    for (int k = 0; k < 32; k++){
        g_offsets[base+k] = tb + pre[k];
    }
}

// ---------------------------------------------------------------- scatter (no atomics)
__global__ void scatter_kernel(){
    int e = blockIdx.x*blockDim.x + threadIdx.x;
    if (e < NEDGE){
        int t = g_knn_idx[e];
        g_bucket[g_offsets[t] + g_cincol[e]] = e;
    }
}

// ---------------------------------------------------------------- colmat
// One warp per target node. Rank-by-counting over incoming-edge keys:
//   count <= 32: key = e            (stable edge-id order, zero-pad tail)
//   count  > 32: key = (d2bits, e)  (lexsort by distance, tie by edge id)
__global__ void __launch_bounds__(256) colmat_kernel(){
    __shared__ unsigned long long s_ck[8][COLCAP];
    int gw   = (blockIdx.x*blockDim.x + threadIdx.x) >> 5;
    int lane = threadIdx.x & 31;
    int wloc = (threadIdx.x >> 5);
    if (gw >= NPTS) return;
    int t     = gw;
    int cnt   = g_counts[t];
    int start = g_offsets[t];
    bool heavy = cnt > KNN;

    if (cnt <= COLCAP){
        for (int s = lane; s < cnt; s += 32){
            int e = g_bucket[start+s];
            unsigned long long key;
            if (heavy) key = (((unsigned long long)__float_as_uint(g_knn_d2[e])) << 32) | (unsigned)e;
            else       key = (unsigned long long)(unsigned)e;
            s_ck[wloc][s] = key;
        }
        g_colmat[t*KNN + lane] = 0;
        __syncwarp();
        for (int s = lane; s < cnt; s += 32){
            unsigned long long my = s_ck[wloc][s];
            int rank = 0;
            for (int k = 0; k < cnt; k++) rank += (s_ck[wloc][k] < my);
            if (rank < KNN){
                unsigned e = heavy ? (unsigned)(my & 0xffffffffULL) : (unsigned)my;
                g_colmat[t*KNN + rank] = (int)e + 1;
            }
        }
    } else {
        // rare fallback: serial extract-min (order-invariant)
        unsigned long long pk = 0ULL;
        unsigned long long mk = ~0ULL;
        for (int s = lane; s < cnt; s += 32){
            int e = g_bucket[start+s];
            unsigned long long key = (((unsigned long long)__float_as_uint(g_knn_d2[e])) << 32) | (unsigned)e;
            key += 1ULL;
            if (key < mk) mk = key;
        }
        for (int r = 0; r < 32; r++){
            unsigned long long rk = mk;
            for (int o = 16; o; o >>= 1){
                unsigned long long ok = __shfl_xor_sync(0xffffffffu, rk, o);
                if (ok < rk) rk = ok;
            }
            int val = 0;
            if (rk != ~0ULL)
                val = (int)(unsigned)((rk - 1ULL) & 0xffffffffULL) + 1;
            if (lane == 0) g_colmat[t*KNN + r] = val;
            if (mk == rk && rk != ~0ULL){
                pk = rk;
                mk = ~0ULL;
                for (int s = lane; s < cnt; s += 32){
                    int e = g_bucket[start+s];
                    unsigned long long key = (((unsigned long long)__float_as_uint(g_knn_d2[e])) << 32) | (unsigned)e;
                    key += 1ULL;
                    if (key > pk && key < mk) mk = key;
                }
            }
        }
    }
}

// ---------------------------------------------------------------- fused output fill (float4 stores)
// quads 0 .. (NEDGE+1)*16-1        : k matrix
// quads (NEDGE+1)*16 .. +(NEDGE+1)*8 : row_idx + col_idx
#define KQUADS  ((NEDGE+1)*16)
#define IQUADS  ((NEDGE+1)*8)
__global__ void fill_kernel(float* __restrict__ out){
    int idx = blockIdx.x*blockDim.x + threadIdx.x;
    if (idx < KQUADS){
        int r  = idx >> 4;
        int c4 = (idx & 15) << 2;
        float4 v = make_float4(0.f, 0.f, 0.f, 0.f);
        if (r > 0){
            float d2 = g_knn_d2[r-1];
            const float4 b = *(const float4*)&g_bcoef[c4];
            asm("ex2.approx.ftz.f32 %0, %1;" : "=f"(v.x) : "f"(-d2*b.x));
            asm("ex2.approx.ftz.f32 %0, %1;" : "=f"(v.y) : "f"(-d2*b.y));
            asm("ex2.approx.ftz.f32 %0, %1;" : "=f"(v.z) : "f"(-d2*b.z));
            asm("ex2.approx.ftz.f32 %0, %1;" : "=f"(v.w) : "f"(-d2*b.w));
        }
        *(float4*)&out[idx << 2] = v;
    } else {
        int t = idx - KQUADS;
        if (t < IQUADS){
            int r = t >> 3;
            int qc = (t & 7) << 2;
            float4 rv = make_float4(0.f,0.f,0.f,0.f);
            float4 cv = make_float4(0.f,0.f,0.f,0.f);
            if (r > 0){
                int e = r - 1;
                int k = (e & ~31) + qc;
                rv = make_float4((float)k, (float)(k+1), (float)(k+2), (float)(k+3));
                int4 cm = *(const int4*)&g_colmat[k];
                cv = make_float4((float)cm.x, (float)cm.y, (float)cm.z, (float)cm.w);
            }
            *(float4*)&out[OFF_ROW + (t << 2)] = rv;
            *(float4*)&out[OFF_COL + (t << 2)] = cv;
        }
    }
}

// ---------------------------------------------------------------- launch
extern "C" void kernel_launch(void* const* d_in, const int* in_sizes, int n_in,
                              void* d_out, int out_size){
    const float* coord = (const float*)d_in[0];
    float* out = (float*)d_out;

    prep_kernel   <<<(NPTS+255)/256, 256>>>(coord);
    knn_kernel    <<<NPTS/QB, 256>>>(out);
    scan_kernel   <<<1, 256>>>();
    scatter_kernel<<<NEDGE/256, 256>>>();
    colmat_kernel <<<NPTS/8, 256>>>();
    fill_kernel   <<<(KQUADS + IQUADS + 255)/256, 256>>>(out);
}

// round 6
// speedup vs baseline: 4.9282x; 1.2158x over previous
#include <cuda_runtime.h>

#define NPTS  8192
#define KNN   32
#define NEDGE (NPTS*KNN)        // 262144
#define NOUT  64
#define QB    8                 // queries per knn block
#define CAPQ  512               // survivor capacity per query
#define COLCAP_S 256            // colmat smem rank-by-count capacity
#define COLCAP_G 512            // per-node incoming-edge buffer capacity
#define TMARGIN 0.01f           // proxy-threshold safety margin

// float32 concat layout of the 4-tuple output
#define OFF_ROW ((NEDGE+1)*NOUT)                  // 16777280
#define OFF_COL (OFF_ROW + (NEDGE+1)*KNN)         // 25165920
#define OFF_IJ  (OFF_COL + (NEDGE+1)*KNN)         // 33554560

#define KQUADS  ((NEDGE+1)*16)
#define IQUADS  ((NEDGE+1)*8)

__device__ float4 g_pts[NPTS];               // {x, y, z, x2}
__device__ float  g_bcoef[NOUT];             // log2(e) / (2*sigma_c^2)
__device__ float  g_knn_d2[NEDGE];
__device__ int    g_counts[NPTS];
__device__ int    g_incoming[NPTS*COLCAP_G]; // per-target incoming edge ids

// exact reference fp32 distance:
// dot = fma(z, fma(y, rn(x*x))) ; d2 = rn(rn(x2i+x2j) - rn(2*dot)) ; clamp 0
__device__ __forceinline__ float ref_d2(const float4 q, const float4 c){
    float dot = __fmul_rn(q.x, c.x);
    dot = __fmaf_rn(q.y, c.y, dot);
    dot = __fmaf_rn(q.z, c.z, dot);
    float t = __fadd_rn(q.w, c.w);
    float v = __fmaf_rn(-2.0f, dot, t);   // == rn(t - rn(2*dot)); 2*dot exact
    return fmaxf(v, 0.0f);
}

// 3-FMA proxy: u = -2qx*cx -2qy*cy -2qz*cz + x2j  ~= d2 - x2i  (+-5e-4)
__device__ __forceinline__ float proxy_u(const float4 m, const float4 c){
    return __fmaf_rn(m.x, c.x, __fmaf_rn(m.y, c.y, __fmaf_rn(m.z, c.z, c.w)));
}

// monotone float -> uint (handles negatives) for unsigned ranking
__device__ __forceinline__ unsigned f2mono(float f){
    unsigned b = __float_as_uint(f);
    return b ^ (((int)b >> 31) | 0x80000000u);
}

// ---------------------------------------------------------------- prep
// x2 = ((rn(x0^2) + rn(x1^2)) + rn(x2^2))  -- XLA mul + sequential reduce
__global__ void prep_kernel(const float* __restrict__ coord){
    int j = blockIdx.x*blockDim.x + threadIdx.x;
    if (j < NPTS){
        float a = coord[3*j+0], b = coord[3*j+1], c = coord[3*j+2];
        float s0 = __fmul_rn(a,a);
        float s1 = __fmul_rn(b,b);
        float s2 = __fmul_rn(c,c);
        float x2 = __fadd_rn(__fadd_rn(s0,s1), s2);
        g_pts[j] = make_float4(a, b, c, x2);
        g_counts[j] = 0;
    }
    if (j < NOUT){
        float sig = 0.1f + (float)j * (4.9f/63.0f);
        g_bcoef[j] = 1.4426950408889634f / (2.0f*sig*sig);
    }
}

// ---------------------------------------------------------------- KNN
// 8 queries per block, 3-FMA proxy scans.
//  Pass 1: per-thread min of proxy u over 32 candidates, per query.
//  Threshold (warp q): T = 32nd-smallest of 64 group-mins (4-thread groups,
//    each covering 128 disjoint candidates => >=32 survivors u<=T), +margin.
//  Pass 2: recompute proxy; survivors get exact ref_d2; compact as keys.
//  Phase D: rank-by-counting -> scatter the 32 smallest (d2, j); each edge
//  also registers itself in its target node's incoming buffer.
__global__ void __launch_bounds__(256) knn_kernel(float* __restrict__ out){
    const int i0   = blockIdx.x * QB;
    const int tid  = threadIdx.x;
    const int lane = tid & 31;
    const int wid  = tid >> 5;

    __shared__ float s_min[QB*256];
    __shared__ float s_T[QB];
    __shared__ int   s_cnt[QB];
    __shared__ unsigned long long s_key[QB*CAPQ];

    float4 Q[QB], M[QB];
#pragma unroll
    for (int q = 0; q < QB; q++){
        Q[q] = g_pts[i0 + q];
        M[q] = make_float4(-2.0f*Q[q].x, -2.0f*Q[q].y, -2.0f*Q[q].z, 0.f);
    }

    const float4* __restrict__ p = g_pts + tid;

    if (tid < QB) s_cnt[tid] = 0;

    // ---- Pass 1: per-thread proxy min per query
    float tmin[QB];
#pragma unroll
    for (int q = 0; q < QB; q++) tmin[q] = 3.4e38f;
#pragma unroll 8
    for (int s = 0; s < 32; s++){
        float4 c = p[s*256];
#pragma unroll
        for (int q = 0; q < QB; q++)
            tmin[q] = fminf(tmin[q], proxy_u(M[q], c));
    }
#pragma unroll
    for (int q = 0; q < QB; q++) s_min[q*256 + tid] = tmin[q];
    __syncthreads();

    // ---- Threshold: warp w handles query w. 64 groups of 4 threads.
    {
        const int q = wid;
        const float* sm = s_min + q*256;
        float ga = fminf(fminf(sm[lane*4+0], sm[lane*4+1]),
                         fminf(sm[lane*4+2], sm[lane*4+3]));
        float gb = fminf(fminf(sm[128+lane*4+0], sm[128+lane*4+1]),
                         fminf(sm[128+lane*4+2], sm[128+lane*4+3]));
        unsigned long long ka = (((unsigned long long)f2mono(ga)) << 6) | (unsigned)lane;
        unsigned long long kb = (((unsigned long long)f2mono(gb)) << 6) | (unsigned)(lane+32);
        unsigned long long* gk = s_key + q*CAPQ;   // scratch (dead after T)
        gk[lane]      = ka;
        gk[lane + 32] = kb;
        __syncwarp();
        int ra = 0, rb = 0;
#pragma unroll
        for (int k = 0; k < 64; k++){
            unsigned long long o = gk[k];
            ra += (o < ka);
            rb += (o < kb);
        }
        if (ra == 31) s_T[q] = ga;
        if (rb == 31) s_T[q] = gb;
    }
    __syncthreads();

    float Tq[QB];
#pragma unroll
    for (int q = 0; q < QB; q++) Tq[q] = s_T[q] + TMARGIN;

    // ---- Pass 2: proxy scan; survivors get exact d2 and are compacted
#pragma unroll 8
    for (int s = 0; s < 32; s++){
        float4 c = p[s*256];
        unsigned j = (unsigned)(s*256 + tid);
#pragma unroll
        for (int q = 0; q < QB; q++){
            float u = proxy_u(M[q], c);
            if (u <= Tq[q]){
                float d2 = ref_d2(Q[q], c);     // exact reference value
                int pos = atomicAdd(&s_cnt[q], 1);
                if (pos < CAPQ)
                    s_key[q*CAPQ + pos] =
                        (((unsigned long long)__float_as_uint(d2)) << 32) | j;
            }
        }
    }
    __syncthreads();

    // ---- Phase D: rank by counting (keys unique via j). Order-invariant.
#pragma unroll
    for (int q = 0; q < QB; q++){
        int cnt = min(s_cnt[q], CAPQ);
        const unsigned long long* keys = s_key + q*CAPQ;
        for (int s0 = tid; s0 < cnt; s0 += 256){
            unsigned long long my = keys[s0];
            int rank = 0;
            for (int k = 0; k < cnt; k++) rank += (keys[k] < my);
            if (rank < KNN){
                int   j  = (int)(unsigned)(my & 0xffffffffULL);
                float d2 = __uint_as_float((unsigned)(my >> 32));
                int e = (i0 + q)*KNN + rank;
                g_knn_d2[e] = d2;
                int pos = atomicAdd(&g_counts[j], 1);
                if (pos < COLCAP_G) g_incoming[j*COLCAP_G + pos] = e;
                out[OFF_IJ + 2*e + 0] = (float)(i0 + q);
                out[OFF_IJ + 2*e + 1] = (float)j;
            }
        }
    }
}

// ---------------------------------------------------------------- colmat + col_idx expansion (fused)
// One warp per target node t. Build its 32-entry colmat row:
//   count <= 32: key = e            (stable edge-id order, zero-pad tail)
//   count  > 32: key = (d2bits, e)  (lexsort by distance, tie by edge id)
// then write the 32 repeated col_idx output rows directly (float4 stores).
__global__ void __launch_bounds__(256) colmat_kernel(float* __restrict__ out){
    __shared__ unsigned long long s_ck[8][COLCAP_S];
    __shared__ float s_val[8][KNN];
    int gw   = (blockIdx.x*blockDim.x + threadIdx.x) >> 5;
    int lane = threadIdx.x & 31;
    int wloc = (threadIdx.x >> 5);
    if (gw >= NPTS) return;
    int t   = gw;
    int cnt = g_counts[t];
    bool heavy = cnt > KNN;
    const int* inc = g_incoming + t*COLCAP_G;

    s_val[wloc][lane] = 0.0f;
    __syncwarp();

    if (cnt <= COLCAP_S){
        for (int s = lane; s < cnt; s += 32){
            int e = inc[s];
            unsigned long long key;
            if (heavy) key = (((unsigned long long)__float_as_uint(g_knn_d2[e])) << 32) | (unsigned)e;
            else       key = (unsigned long long)(unsigned)e;
            s_ck[wloc][s] = key;
        }
        __syncwarp();
        for (int s = lane; s < cnt; s += 32){
            unsigned long long my = s_ck[wloc][s];
            int rank = 0;
            for (int k = 0; k < cnt; k++) rank += (s_ck[wloc][k] < my);
            if (rank < KNN){
                unsigned e = heavy ? (unsigned)(my & 0xffffffffULL) : (unsigned)my;
                s_val[wloc][rank] = (float)((int)e + 1);
            }
        }
        __syncwarp();
    } else {
        // rare fallback (256 < cnt <= 512): serial extract-min, order-invariant
        int cc = min(cnt, COLCAP_G);
        unsigned long long pk = 0ULL;
        unsigned long long mk = ~0ULL;
        for (int s = lane; s < cc; s += 32){
            int e = inc[s];
            unsigned long long key = (((unsigned long long)__float_as_uint(g_knn_d2[e])) << 32) | (unsigned)e;
            key += 1ULL;
            if (key < mk) mk = key;
        }
        for (int r = 0; r < 32; r++){
            unsigned long long rk = mk;
            for (int o = 16; o; o >>= 1){
                unsigned long long ok = __shfl_xor_sync(0xffffffffu, rk, o);
                if (ok < rk) rk = ok;
            }
            if (lane == 0 && rk != ~0ULL)
                s_val[wloc][r] = (float)((int)(unsigned)((rk - 1ULL) & 0xffffffffULL) + 1);
            if (mk == rk && rk != ~0ULL){
                pk = rk;
                mk = ~0ULL;
                for (int s = lane; s < cc; s += 32){
                    int e = inc[s];
                    unsigned long long key = (((unsigned long long)__float_as_uint(g_knn_d2[e])) << 32) | (unsigned)e;
                    key += 1ULL;
                    if (key > pk && key < mk) mk = key;
                }
            }
        }
        __syncwarp();
    }

    // write 32 output rows (rows t*32+1 .. t*32+32), 8 float4 per row
    const float4* src = (const float4*)(&s_val[wloc][0]);
#pragma unroll
    for (int kq = 0; kq < 8; kq++){
        int lin  = lane + 32*kq;       // 0..255
        int row  = lin >> 3;
        int quad = lin & 7;
        *(float4*)&out[OFF_COL + (unsigned)(t*KNN + row + 1)*KNN + quad*4] = src[quad];
    }
}

// ---------------------------------------------------------------- k matrix fill (float4 stores)
__global__ void kfill_kernel(float* __restrict__ out){
    int idx = blockIdx.x*blockDim.x + threadIdx.x;
    if (idx >= KQUADS) return;
    int r  = idx >> 4;
    int c4 = (idx & 15) << 2;
    float4 v = make_float4(0.f, 0.f, 0.f, 0.f);
    if (r > 0){
        float d2 = g_knn_d2[r-1];
        const float4 b = *(const float4*)&g_bcoef[c4];
        asm("ex2.approx.ftz.f32 %0, %1;" : "=f"(v.x) : "f"(-d2*b.x));
        asm("ex2.approx.ftz.f32 %0, %1;" : "=f"(v.y) : "f"(-d2*b.y));
        asm("ex2.approx.ftz.f32 %0, %1;" : "=f"(v.z) : "f"(-d2*b.z));
        asm("ex2.approx.ftz.f32 %0, %1;" : "=f"(v.w) : "f"(-d2*b.w));
    }
    *(float4*)&out[idx << 2] = v;
}

// ---------------------------------------------------------------- row_idx fill (no dependencies)
// also zeroes row 0 of the col_idx region
__global__ void rowfill_kernel(float* __restrict__ out){
    int idx = blockIdx.x*blockDim.x + threadIdx.x;
    if (idx < IQUADS){
        int r = idx >> 3;
        int qc = (idx & 7) << 2;
        float4 rv = make_float4(0.f,0.f,0.f,0.f);
        if (r > 0){
            int e = r - 1;
            int k = (e & ~31) + qc;
            rv = make_float4((float)k, (float)(k+1), (float)(k+2), (float)(k+3));
        }
        *(float4*)&out[OFF_ROW + (idx << 2)] = rv;
    } else if (idx < IQUADS + 8){
        *(float4*)&out[OFF_COL + ((idx - IQUADS) << 2)] =
            make_float4(0.f,0.f,0.f,0.f);
    }
}

// ---------------------------------------------------------------- launch
// DAG (graph-capturable multi-stream fork/join):
//   main:  prep -> knn ------------------> colmat(+col_idx) -> [wait s2]
//   s2:    rowfill (no deps)  [after knn:] kfill
extern "C" void kernel_launch(void* const* d_in, const int* in_sizes, int n_in,
                              void* d_out, int out_size){
    const float* coord = (const float*)d_in[0];
    float* out = (float*)d_out;

    static cudaStream_t s2 = nullptr;
    static cudaEvent_t  evA = nullptr, evB = nullptr, evC = nullptr;
    if (s2 == nullptr){
        cudaStreamCreateWithFlags(&s2, cudaStreamNonBlocking);
        cudaEventCreateWithFlags(&evA, cudaEventDisableTiming);
        cudaEventCreateWithFlags(&evB, cudaEventDisableTiming);
        cudaEventCreateWithFlags(&evC, cudaEventDisableTiming);
    }

    // fork: s2 branches off the main (capture-origin) stream
    cudaEventRecord(evA, (cudaStream_t)0);
    cudaStreamWaitEvent(s2, evA, 0);

    rowfill_kernel<<<(IQUADS + 8 + 255)/256, 256, 0, s2>>>(out);

    prep_kernel<<<(NPTS+255)/256, 256>>>(coord);
    knn_kernel <<<NPTS/QB, 256>>>(out);

    // k fill depends only on knn results; run it on s2 concurrent with colmat
    cudaEventRecord(evB, (cudaStream_t)0);
    cudaStreamWaitEvent(s2, evB, 0);
    kfill_kernel<<<(KQUADS + 255)/256, 256, 0, s2>>>(out);
    cudaEventRecord(evC, s2);

    colmat_kernel<<<NPTS/8, 256>>>(out);

    // join
    cudaStreamWaitEvent((cudaStream_t)0, evC, 0);
}